// round 11
// baseline (speedup 1.0000x reference)
#include <cuda_runtime.h>

#define NN    100000
#define EE    1600000
#define HID   64
#define HID2  128
#define EDIM  16
#define INDIM 32

// ---------------- scratch (device globals; no allocation) ----------------
__device__ float  g_hA[NN * HID];
__device__ float  g_hB[NN * HID];
__device__ float  g_tmp[NN * HID];
__device__ int    g_deg[NN];
__device__ int    g_cnt[NN];
__device__ int    g_rowptr[NN + 1];
__device__ int    g_blksum[256];
__device__ int    g_srcp[EE];          // src index permuted to CSR order
__device__ float4 g_eap[EE * 4];       // edge_attr permuted to CSR order (64 B/edge)

// ---------------- CSR build ----------------
__global__ void k_zero(int N) {
    int i = blockIdx.x * blockDim.x + threadIdx.x;
    if (i < N) { g_deg[i] = 0; g_cnt[i] = 0; }
}

__global__ void k_hist(const int* __restrict__ dst, int E) {
    int e = blockIdx.x * blockDim.x + threadIdx.x;
    if (e < E) atomicAdd(&g_deg[dst[e]], 1);
}

__global__ void k_scan1(int N) {
    __shared__ int sh[1024];
    int i = blockIdx.x * 1024 + threadIdx.x;
    int v = (i < N) ? g_deg[i] : 0;
    sh[threadIdx.x] = v;
    __syncthreads();
    for (int off = 1; off < 1024; off <<= 1) {
        int add = (threadIdx.x >= off) ? sh[threadIdx.x - off] : 0;
        __syncthreads();
        sh[threadIdx.x] += add;
        __syncthreads();
    }
    if (i < N) g_rowptr[i] = sh[threadIdx.x] - v;     // exclusive
    if (threadIdx.x == 1023) g_blksum[blockIdx.x] = sh[1023];
}

__global__ void k_scan2(int B) {
    if (blockIdx.x == 0 && threadIdx.x == 0) {
        int acc = 0;
        for (int b = 0; b < B; b++) { int t = g_blksum[b]; g_blksum[b] = acc; acc += t; }
    }
}

__global__ void k_scan3(int N, int E) {
    int i = blockIdx.x * 1024 + threadIdx.x;
    if (i < N) g_rowptr[i] += g_blksum[blockIdx.x];
    if (i == 0) g_rowptr[N] = E;
}

// scatter: build CSR-permuted src and edge_attr streams
__global__ void k_scatter(const int* __restrict__ src, const int* __restrict__ dst,
                          const float4* __restrict__ ea, int E) {
    int e = blockIdx.x * blockDim.x + threadIdx.x;
    if (e >= E) return;
    int d = dst[e];
    int p = g_rowptr[d] + atomicAdd(&g_cnt[d], 1);
    g_srcp[p] = src[e];
    float4 a0 = __ldg(ea + e * 4 + 0);
    float4 a1 = __ldg(ea + e * 4 + 1);
    float4 a2 = __ldg(ea + e * 4 + 2);
    float4 a3 = __ldg(ea + e * 4 + 3);
    g_eap[p * 4 + 0] = a0;
    g_eap[p * 4 + 1] = a1;
    g_eap[p * 4 + 2] = a2;
    g_eap[p * 4 + 3] = a3;
}

// ---------------- input linear: h = x @ src_w + src_b ----------------
__global__ void k_inlin(const float* __restrict__ x, const float* __restrict__ w,
                        const float* __restrict__ b, int N) {
    int idx = blockIdx.x * blockDim.x + threadIdx.x;
    if (idx >= N * HID) return;
    int n = idx >> 6, c = idx & 63;
    const float* xr = x + n * INDIM;
    float acc = __ldg(&b[c]);
#pragma unroll
    for (int k = 0; k < INDIM; k++)
        acc = fmaf(__ldg(&xr[k]), __ldg(&w[k * HID + c]), acc);
    g_hA[idx] = acc;
}

// ---------------- aggregation: 2 warps per node, 1 channel/lane, 4-edge pipe -
// dir=0: read g_hA; dir=1: read g_hB. Writes g_tmp.
__device__ __forceinline__ void agg_edge1(
    float h, const float4* __restrict__ ea, const float* __restrict__ ewr,
    float eb, float& s, float& t)
{
    float4 a0 = __ldg(ea + 0), a1 = __ldg(ea + 1);
    float4 a2 = __ldg(ea + 2), a3 = __ldg(ea + 3);
    float av[16] = {a0.x, a0.y, a0.z, a0.w, a1.x, a1.y, a1.z, a1.w,
                    a2.x, a2.y, a2.z, a2.w, a3.x, a3.y, a3.z, a3.w};
    float v = eb;
#pragma unroll
    for (int k = 0; k < EDIM; k++)
        v = fmaf(av[k], ewr[k], v);
    // msg = relu(h+v); eps added at the end (softmax shift-invariant).
    // No max-subtraction: msg >= 0 and O(10) -> expf cannot overflow.
    float r = fmaxf(h + v, 0.f);
    float w = __expf(r);
    s += w;
    t = fmaf(r, w, t);
}

__global__ void __launch_bounds__(256)
k_agg(int dir, const float* __restrict__ ew, const float* __restrict__ ebias, int N) {
    const float* hin = dir ? g_hB : g_hA;
    int warp = threadIdx.x >> 5, lane = threadIdx.x & 31;
    int n = blockIdx.x * 4 + (warp >> 1);
    if (n >= N) return;
    int c = ((warp & 1) << 5) + lane;   // this lane's single channel

    // preload ew column for this lane's channel (16 regs)
    float ewr[EDIM];
#pragma unroll
    for (int k = 0; k < EDIM; k++)
        ewr[k] = __ldg(&ew[k * HID + c]);
    float eb = __ldg(&ebias[c]);
    float hs = __ldg(&hin[n * HID + c]);     // self feature, hoisted

    int beg = g_rowptr[n], end = g_rowptr[n + 1];
    float s = 0.f, t = 0.f;

    int i = beg;
    // 4-edge pipelined main loop: batch the random h-gathers up front
    for (; i + 4 <= end; i += 4) {
        int sv0 = __ldg(&g_srcp[i + 0]);
        int sv1 = __ldg(&g_srcp[i + 1]);
        int sv2 = __ldg(&g_srcp[i + 2]);
        int sv3 = __ldg(&g_srcp[i + 3]);
        float h0 = __ldg(&hin[sv0 * HID + c]);
        float h1 = __ldg(&hin[sv1 * HID + c]);
        float h2 = __ldg(&hin[sv2 * HID + c]);
        float h3 = __ldg(&hin[sv3 * HID + c]);
        agg_edge1(h0, g_eap + (size_t)(i + 0) * 4, ewr, eb, s, t);
        agg_edge1(h1, g_eap + (size_t)(i + 1) * 4, ewr, eb, s, t);
        agg_edge1(h2, g_eap + (size_t)(i + 2) * 4, ewr, eb, s, t);
        agg_edge1(h3, g_eap + (size_t)(i + 3) * 4, ewr, eb, s, t);
    }
    for (; i < end; i++) {
        int sv = __ldg(&g_srcp[i]);
        float h = __ldg(&hin[sv * HID + c]);
        agg_edge1(h, g_eap + (size_t)i * 4, ewr, eb, s, t);
    }

    float o = (s > 0.f ? __fdividef(t, s) + 1e-7f : 0.f) + hs;
    g_tmp[n * HID + c] = o;
}

// ---------------- MLP: Linear(64->128) -> BN -> ReLU -> Linear(128->64) -> ReLU
// reads g_tmp; dir=0: write g_hB; dir=1: write g_hA.
// 32 nodes per block, 256 threads, register-tiled, float4 LDS
__global__ void __launch_bounds__(256)
k_mlp(int dir,
      const float* __restrict__ w1, const float* __restrict__ b1,
      const float* __restrict__ gam, const float* __restrict__ bet,
      const float* __restrict__ w2, const float* __restrict__ b2, int N) {
    float* outp = dir ? g_hA : g_hB;
    __shared__ float s_in[32][HID];     // 8 KB
    __shared__ float s_hh[32][HID2];    // 16 KB
    int tid = threadIdx.x;
    int base = blockIdx.x * 32;

    // stage 32 node rows (zero-fill past N)
    {
        const float4* src4 = (const float4*)(g_tmp + base * HID);
        float4* dst4 = (float4*)&s_in[0][0];
        long limit4 = (long)(N - base) * (HID / 4);
#pragma unroll
        for (int t = 0; t < 2; t++) {
            int i = tid + t * 256;
            dst4[i] = (i < limit4) ? __ldg(src4 + i) : make_float4(0.f, 0.f, 0.f, 0.f);
        }
    }
    __syncthreads();

    // phase 1: hh = relu(BN(in @ w1 + b1)); thread: 8 nodes x 2 adjacent j
    {
        int jp  = tid & 63;
        int grp = tid >> 6;
        float2 bb = __ldg((const float2*)b1 + jp);
        float a0[8], a1[8];
#pragma unroll
        for (int u = 0; u < 8; u++) { a0[u] = bb.x; a1[u] = bb.y; }
#pragma unroll
        for (int k4 = 0; k4 < HID; k4 += 4) {
            float2 w0 = __ldg((const float2*)(w1 + (k4 + 0) * HID2) + jp);
            float2 w1v = __ldg((const float2*)(w1 + (k4 + 1) * HID2) + jp);
            float2 w2v = __ldg((const float2*)(w1 + (k4 + 2) * HID2) + jp);
            float2 w3 = __ldg((const float2*)(w1 + (k4 + 3) * HID2) + jp);
#pragma unroll
            for (int u = 0; u < 8; u++) {
                float4 xv = *(const float4*)&s_in[grp * 8 + u][k4];
                a0[u] = fmaf(xv.x, w0.x, a0[u]);
                a1[u] = fmaf(xv.x, w0.y, a1[u]);
                a0[u] = fmaf(xv.y, w1v.x, a0[u]);
                a1[u] = fmaf(xv.y, w1v.y, a1[u]);
                a0[u] = fmaf(xv.z, w2v.x, a0[u]);
                a1[u] = fmaf(xv.z, w2v.y, a1[u]);
                a0[u] = fmaf(xv.w, w3.x, a0[u]);
                a1[u] = fmaf(xv.w, w3.y, a1[u]);
            }
        }
        const float BNC = 0.9999950000375f;    // 1/sqrt(1+1e-5)
        float2 gm = __ldg((const float2*)gam + jp);
        float2 bt = __ldg((const float2*)bet + jp);
        float g0 = gm.x * BNC, g1 = gm.y * BNC;
#pragma unroll
        for (int u = 0; u < 8; u++) {
            float2 hv;
            hv.x = fmaxf(fmaf(a0[u], g0, bt.x), 0.f);
            hv.y = fmaxf(fmaf(a1[u], g1, bt.y), 0.f);
            *((float2*)&s_hh[grp * 8 + u][0] + jp) = hv;
        }
    }
    __syncthreads();

    // phase 2: y = relu(hh @ w2 + b2); thread: 4 nodes x 2 adjacent c
    {
        int cp  = tid & 31;
        int grp = tid >> 5;
        float2 bb = __ldg((const float2*)b2 + cp);
        float a0[4], a1[4];
#pragma unroll
        for (int u = 0; u < 4; u++) { a0[u] = bb.x; a1[u] = bb.y; }
#pragma unroll
        for (int k4 = 0; k4 < HID2; k4 += 4) {
            float2 w0 = __ldg((const float2*)(w2 + (k4 + 0) * HID) + cp);
            float2 w1v = __ldg((const float2*)(w2 + (k4 + 1) * HID) + cp);
            float2 w2v = __ldg((const float2*)(w2 + (k4 + 2) * HID) + cp);
            float2 w3 = __ldg((const float2*)(w2 + (k4 + 3) * HID) + cp);
#pragma unroll
            for (int u = 0; u < 4; u++) {
                float4 xv = *(const float4*)&s_hh[grp * 4 + u][k4];
                a0[u] = fmaf(xv.x, w0.x, a0[u]);
                a1[u] = fmaf(xv.x, w0.y, a1[u]);
                a0[u] = fmaf(xv.y, w1v.x, a0[u]);
                a1[u] = fmaf(xv.y, w1v.y, a1[u]);
                a0[u] = fmaf(xv.z, w2v.x, a0[u]);
                a1[u] = fmaf(xv.z, w2v.y, a1[u]);
                a0[u] = fmaf(xv.w, w3.x, a0[u]);
                a1[u] = fmaf(xv.w, w3.y, a1[u]);
            }
        }
#pragma unroll
        for (int u = 0; u < 4; u++) {
            int node = base + grp * 4 + u;
            if (node < N) {
                float2 ov;
                ov.x = fmaxf(a0[u], 0.f);   // outer relu
                ov.y = fmaxf(a1[u], 0.f);
                *((float2*)(outp + node * HID) + cp) = ov;
            }
        }
    }
}

// ---------------- head ----------------
__global__ void k_head(const float* __restrict__ gfeat, const int* __restrict__ ngp,
                       const float* __restrict__ hw, const float* __restrict__ hb,
                       float* __restrict__ out, int N, int gfd) {
    int n = blockIdx.x * blockDim.x + threadIdx.x;
    if (n >= N) return;
    const float* h = g_hA;   // final features land in A (A->B->A)
    float acc = __ldg(&hb[0]);
#pragma unroll 8
    for (int c = 0; c < HID; c++)
        acc = fmaf(h[n * HID + c], __ldg(&hw[c]), acc);
    int G = *ngp;
    int npg = N / G;
    int g = n / npg, r = n - g * npg;
    for (int d = 0; d < gfd; d++)
        acc = fmaf(__ldg(&gfeat[(g * gfd + d) * npg + r]), __ldg(&hw[HID + d]), acc);
    out[n] = acc;
}

// ---------------- launch ----------------
extern "C" void kernel_launch(void* const* d_in, const int* in_sizes, int n_in,
                              void* d_out, int out_size) {
    const float* x     = (const float*)d_in[0];
    const int*   eidx  = (const int*)d_in[1];
    const float* eattr = (const float*)d_in[2];
    const int*   ngp   = (const int*)d_in[3];
    const float* gfeat = (const float*)d_in[4];
    const float* src_w = (const float*)d_in[5];
    const float* src_b = (const float*)d_in[6];

    int N   = in_sizes[0] / INDIM;
    int E   = in_sizes[1] / 2;
    int gfd = in_sizes[4] / N;

    const int* src = eidx;
    const int* dst = eidx + E;

    // CSR build + permuted edge streams
    k_zero<<<(N + 255) / 256, 256>>>(N);
    k_hist<<<(E + 255) / 256, 256>>>(dst, E);
    int nb = (N + 1023) / 1024;
    k_scan1<<<nb, 1024>>>(N);
    k_scan2<<<1, 32>>>(nb);
    k_scan3<<<nb, 1024>>>(N, E);
    k_scatter<<<(E + 255) / 256, 256>>>(src, dst, (const float4*)eattr, E);

    // h0 = x @ src_w + src_b   (writes g_hA)
    k_inlin<<<(N * HID + 255) / 256, 256>>>(x, src_w, src_b, N);

    // layer 0: hA -> tmp -> hB
    k_agg<<<(N + 3) / 4, 256>>>(0, (const float*)d_in[7], (const float*)d_in[8], N);
    k_mlp<<<(N + 31) / 32, 256>>>(0,
        (const float*)d_in[9],  (const float*)d_in[10],
        (const float*)d_in[11], (const float*)d_in[12],
        (const float*)d_in[13], (const float*)d_in[14], N);

    // layer 1: hB -> tmp -> hA
    k_agg<<<(N + 3) / 4, 256>>>(1, (const float*)d_in[15], (const float*)d_in[16], N);
    k_mlp<<<(N + 31) / 32, 256>>>(1,
        (const float*)d_in[17], (const float*)d_in[18],
        (const float*)d_in[19], (const float*)d_in[20],
        (const float*)d_in[21], (const float*)d_in[22], N);

    // head
    k_head<<<(N + 255) / 256, 256>>>(gfeat, ngp,
        (const float*)d_in[23], (const float*)d_in[24],
        (float*)d_out, N, gfd);
    (void)n_in; (void)out_size;
}

// round 12
// speedup vs baseline: 1.5303x; 1.5303x over previous
#include <cuda_runtime.h>

#define NN    100000
#define EE    1600000
#define HID   64
#define HID2  128
#define EDIM  16
#define INDIM 32

// ---------------- scratch (device globals; no allocation) ----------------
__device__ float  g_hA[NN * HID];
__device__ float  g_hB[NN * HID];
__device__ float  g_tmp[NN * HID];
__device__ int    g_deg[NN];
__device__ int    g_cnt[NN];
__device__ int    g_rowptr[NN + 1];
__device__ int    g_blksum[256];
__device__ int    g_srcp[EE];          // src index permuted to CSR order
__device__ float4 g_eap[EE * 4];       // edge_attr permuted to CSR order (64 B/edge)

// ---------------- CSR build ----------------
__global__ void k_zero(int N) {
    int i = blockIdx.x * blockDim.x + threadIdx.x;
    if (i < N) { g_deg[i] = 0; g_cnt[i] = 0; }
}

__global__ void k_hist(const int* __restrict__ dst, int E) {
    int e = blockIdx.x * blockDim.x + threadIdx.x;
    if (e < E) atomicAdd(&g_deg[dst[e]], 1);
}

__global__ void k_scan1(int N) {
    __shared__ int sh[1024];
    int i = blockIdx.x * 1024 + threadIdx.x;
    int v = (i < N) ? g_deg[i] : 0;
    sh[threadIdx.x] = v;
    __syncthreads();
    for (int off = 1; off < 1024; off <<= 1) {
        int add = (threadIdx.x >= off) ? sh[threadIdx.x - off] : 0;
        __syncthreads();
        sh[threadIdx.x] += add;
        __syncthreads();
    }
    if (i < N) g_rowptr[i] = sh[threadIdx.x] - v;     // exclusive
    if (threadIdx.x == 1023) g_blksum[blockIdx.x] = sh[1023];
}

__global__ void k_scan2(int B) {
    if (blockIdx.x == 0 && threadIdx.x == 0) {
        int acc = 0;
        for (int b = 0; b < B; b++) { int t = g_blksum[b]; g_blksum[b] = acc; acc += t; }
    }
}

__global__ void k_scan3(int N, int E) {
    int i = blockIdx.x * 1024 + threadIdx.x;
    if (i < N) g_rowptr[i] += g_blksum[blockIdx.x];
    if (i == 0) g_rowptr[N] = E;
}

// scatter: build CSR-permuted src and edge_attr streams
__global__ void k_scatter(const int* __restrict__ src, const int* __restrict__ dst,
                          const float4* __restrict__ ea, int E) {
    int e = blockIdx.x * blockDim.x + threadIdx.x;
    if (e >= E) return;
    int d = dst[e];
    int p = g_rowptr[d] + atomicAdd(&g_cnt[d], 1);
    g_srcp[p] = src[e];
    float4 a0 = __ldg(ea + e * 4 + 0);
    float4 a1 = __ldg(ea + e * 4 + 1);
    float4 a2 = __ldg(ea + e * 4 + 2);
    float4 a3 = __ldg(ea + e * 4 + 3);
    g_eap[p * 4 + 0] = a0;
    g_eap[p * 4 + 1] = a1;
    g_eap[p * 4 + 2] = a2;
    g_eap[p * 4 + 3] = a3;
}

// ---------------- input linear: h = x @ src_w + src_b ----------------
__global__ void k_inlin(const float* __restrict__ x, const float* __restrict__ w,
                        const float* __restrict__ b, int N) {
    int idx = blockIdx.x * blockDim.x + threadIdx.x;
    if (idx >= N * HID) return;
    int n = idx >> 6, c = idx & 63;
    const float* xr = x + n * INDIM;
    float acc = __ldg(&b[c]);
#pragma unroll
    for (int k = 0; k < INDIM; k++)
        acc = fmaf(__ldg(&xr[k]), __ldg(&w[k * HID + c]), acc);
    g_hA[idx] = acc;
}

// ---------------- aggregation: warp-per-node, 4-edge pipeline + srcp prefetch
// dir=0: read g_hA; dir=1: read g_hB. Writes g_tmp.
// lane owns channels (2*lane, 2*lane+1).
__device__ __forceinline__ void agg_edge(
    float2 h, const float4* __restrict__ ea, const float2* __restrict__ ewr,
    float eb0, float eb1, float& s0, float& s1, float& t0, float& t1)
{
    float4 a0 = __ldg(ea + 0), a1 = __ldg(ea + 1);
    float4 a2 = __ldg(ea + 2), a3 = __ldg(ea + 3);
    float av[16] = {a0.x, a0.y, a0.z, a0.w, a1.x, a1.y, a1.z, a1.w,
                    a2.x, a2.y, a2.z, a2.w, a3.x, a3.y, a3.z, a3.w};
    float v0 = eb0, v1 = eb1;
#pragma unroll
    for (int k = 0; k < EDIM; k++) {
        v0 = fmaf(av[k], ewr[k].x, v0);
        v1 = fmaf(av[k], ewr[k].y, v1);
    }
    // msg = relu(h+v); eps added at the end (softmax shift-invariant).
    // No max-subtraction: msg >= 0 and O(10) -> expf cannot overflow.
    float r0 = fmaxf(h.x + v0, 0.f);
    float r1 = fmaxf(h.y + v1, 0.f);
    float w0 = __expf(r0);
    float w1 = __expf(r1);
    s0 += w0;
    s1 += w1;
    t0 = fmaf(r0, w0, t0);
    t1 = fmaf(r1, w1, t1);
}

__global__ void __launch_bounds__(256)
k_agg(int dir, const float* __restrict__ ew, const float* __restrict__ ebias, int N) {
    const float* hin = dir ? g_hB : g_hA;
    int warp = threadIdx.x >> 5, lane = threadIdx.x & 31;
    int n = blockIdx.x * 8 + warp;
    if (n >= N) return;

    // preload ew columns for this lane's two channels
    float2 ewr[EDIM];
#pragma unroll
    for (int k = 0; k < EDIM; k++)
        ewr[k] = __ldg((const float2*)(ew + k * HID) + lane);
    float2 eb = __ldg((const float2*)ebias + lane);
    float2 hs = __ldg((const float2*)(hin + n * HID) + lane);   // self feature, hoisted

    int beg = g_rowptr[n], end = g_rowptr[n + 1];
    float s0 = 0.f, s1 = 0.f, t0 = 0.f, t1 = 0.f;

    int i = beg;
    // software-pipelined 4-edge loop: srcp for batch k+1 prefetched during batch k
    bool have = (i + 4 <= end);
    int sv0 = 0, sv1 = 0, sv2 = 0, sv3 = 0;
    if (have) {
        sv0 = __ldg(&g_srcp[i + 0]);
        sv1 = __ldg(&g_srcp[i + 1]);
        sv2 = __ldg(&g_srcp[i + 2]);
        sv3 = __ldg(&g_srcp[i + 3]);
    }
    while (have) {
        // issue the 4 random h-gathers first
        float2 h0 = __ldg((const float2*)(hin + sv0 * HID) + lane);
        float2 h1 = __ldg((const float2*)(hin + sv1 * HID) + lane);
        float2 h2 = __ldg((const float2*)(hin + sv2 * HID) + lane);
        float2 h3 = __ldg((const float2*)(hin + sv3 * HID) + lane);
        // prefetch next batch's srcp while current h-gathers are in flight
        int j = i + 4;
        bool nxt = (j + 4 <= end);
        int p0 = sv0, p1 = sv1, p2 = sv2, p3 = sv3;
        if (nxt) {
            p0 = __ldg(&g_srcp[j + 0]);
            p1 = __ldg(&g_srcp[j + 1]);
            p2 = __ldg(&g_srcp[j + 2]);
            p3 = __ldg(&g_srcp[j + 3]);
        }
        // compute current batch
        agg_edge(h0, g_eap + (size_t)(i + 0) * 4, ewr, eb.x, eb.y, s0, s1, t0, t1);
        agg_edge(h1, g_eap + (size_t)(i + 1) * 4, ewr, eb.x, eb.y, s0, s1, t0, t1);
        agg_edge(h2, g_eap + (size_t)(i + 2) * 4, ewr, eb.x, eb.y, s0, s1, t0, t1);
        agg_edge(h3, g_eap + (size_t)(i + 3) * 4, ewr, eb.x, eb.y, s0, s1, t0, t1);
        sv0 = p0; sv1 = p1; sv2 = p2; sv3 = p3;
        i = j;
        have = nxt;
    }
    // scalar tail
    for (; i < end; i++) {
        int sv = __ldg(&g_srcp[i]);
        float2 h = __ldg((const float2*)(hin + sv * HID) + lane);
        agg_edge(h, g_eap + (size_t)i * 4, ewr, eb.x, eb.y, s0, s1, t0, t1);
    }

    float o0 = (s0 > 0.f ? __fdividef(t0, s0) + 1e-7f : 0.f) + hs.x;
    float o1 = (s1 > 0.f ? __fdividef(t1, s1) + 1e-7f : 0.f) + hs.y;
    *((float2*)(g_tmp + n * HID) + lane) = make_float2(o0, o1);
}

// ---------------- MLP: Linear(64->128) -> BN -> ReLU -> Linear(128->64) -> ReLU
// reads g_tmp; dir=0: write g_hB; dir=1: write g_hA.
// 32 nodes per block, 256 threads, register-tiled, float4 LDS
__global__ void __launch_bounds__(256)
k_mlp(int dir,
      const float* __restrict__ w1, const float* __restrict__ b1,
      const float* __restrict__ gam, const float* __restrict__ bet,
      const float* __restrict__ w2, const float* __restrict__ b2, int N) {
    float* outp = dir ? g_hA : g_hB;
    __shared__ float s_in[32][HID];     // 8 KB
    __shared__ float s_hh[32][HID2];    // 16 KB
    int tid = threadIdx.x;
    int base = blockIdx.x * 32;

    // stage 32 node rows (zero-fill past N)
    {
        const float4* src4 = (const float4*)(g_tmp + base * HID);
        float4* dst4 = (float4*)&s_in[0][0];
        long limit4 = (long)(N - base) * (HID / 4);
#pragma unroll
        for (int t = 0; t < 2; t++) {
            int i = tid + t * 256;
            dst4[i] = (i < limit4) ? __ldg(src4 + i) : make_float4(0.f, 0.f, 0.f, 0.f);
        }
    }
    __syncthreads();

    // phase 1: hh = relu(BN(in @ w1 + b1)); thread: 8 nodes x 2 adjacent j
    {
        int jp  = tid & 63;
        int grp = tid >> 6;
        float2 bb = __ldg((const float2*)b1 + jp);
        float a0[8], a1[8];
#pragma unroll
        for (int u = 0; u < 8; u++) { a0[u] = bb.x; a1[u] = bb.y; }
#pragma unroll
        for (int k4 = 0; k4 < HID; k4 += 4) {
            float2 w0 = __ldg((const float2*)(w1 + (k4 + 0) * HID2) + jp);
            float2 w1v = __ldg((const float2*)(w1 + (k4 + 1) * HID2) + jp);
            float2 w2v = __ldg((const float2*)(w1 + (k4 + 2) * HID2) + jp);
            float2 w3 = __ldg((const float2*)(w1 + (k4 + 3) * HID2) + jp);
#pragma unroll
            for (int u = 0; u < 8; u++) {
                float4 xv = *(const float4*)&s_in[grp * 8 + u][k4];
                a0[u] = fmaf(xv.x, w0.x, a0[u]);
                a1[u] = fmaf(xv.x, w0.y, a1[u]);
                a0[u] = fmaf(xv.y, w1v.x, a0[u]);
                a1[u] = fmaf(xv.y, w1v.y, a1[u]);
                a0[u] = fmaf(xv.z, w2v.x, a0[u]);
                a1[u] = fmaf(xv.z, w2v.y, a1[u]);
                a0[u] = fmaf(xv.w, w3.x, a0[u]);
                a1[u] = fmaf(xv.w, w3.y, a1[u]);
            }
        }
        const float BNC = 0.9999950000375f;    // 1/sqrt(1+1e-5)
        float2 gm = __ldg((const float2*)gam + jp);
        float2 bt = __ldg((const float2*)bet + jp);
        float g0 = gm.x * BNC, g1 = gm.y * BNC;
#pragma unroll
        for (int u = 0; u < 8; u++) {
            float2 hv;
            hv.x = fmaxf(fmaf(a0[u], g0, bt.x), 0.f);
            hv.y = fmaxf(fmaf(a1[u], g1, bt.y), 0.f);
            *((float2*)&s_hh[grp * 8 + u][0] + jp) = hv;
        }
    }
    __syncthreads();

    // phase 2: y = relu(hh @ w2 + b2); thread: 4 nodes x 2 adjacent c
    {
        int cp  = tid & 31;
        int grp = tid >> 5;
        float2 bb = __ldg((const float2*)b2 + cp);
        float a0[4], a1[4];
#pragma unroll
        for (int u = 0; u < 4; u++) { a0[u] = bb.x; a1[u] = bb.y; }
#pragma unroll
        for (int k4 = 0; k4 < HID2; k4 += 4) {
            float2 w0 = __ldg((const float2*)(w2 + (k4 + 0) * HID) + cp);
            float2 w1v = __ldg((const float2*)(w2 + (k4 + 1) * HID) + cp);
            float2 w2v = __ldg((const float2*)(w2 + (k4 + 2) * HID) + cp);
            float2 w3 = __ldg((const float2*)(w2 + (k4 + 3) * HID) + cp);
#pragma unroll
            for (int u = 0; u < 4; u++) {
                float4 xv = *(const float4*)&s_hh[grp * 4 + u][k4];
                a0[u] = fmaf(xv.x, w0.x, a0[u]);
                a1[u] = fmaf(xv.x, w0.y, a1[u]);
                a0[u] = fmaf(xv.y, w1v.x, a0[u]);
                a1[u] = fmaf(xv.y, w1v.y, a1[u]);
                a0[u] = fmaf(xv.z, w2v.x, a0[u]);
                a1[u] = fmaf(xv.z, w2v.y, a1[u]);
                a0[u] = fmaf(xv.w, w3.x, a0[u]);
                a1[u] = fmaf(xv.w, w3.y, a1[u]);
            }
        }
#pragma unroll
        for (int u = 0; u < 4; u++) {
            int node = base + grp * 4 + u;
            if (node < N) {
                float2 ov;
                ov.x = fmaxf(a0[u], 0.f);   // outer relu
                ov.y = fmaxf(a1[u], 0.f);
                *((float2*)(outp + node * HID) + cp) = ov;
            }
        }
    }
}

// ---------------- head ----------------
__global__ void k_head(const float* __restrict__ gfeat, const int* __restrict__ ngp,
                       const float* __restrict__ hw, const float* __restrict__ hb,
                       float* __restrict__ out, int N, int gfd) {
    int n = blockIdx.x * blockDim.x + threadIdx.x;
    if (n >= N) return;
    const float* h = g_hA;   // final features land in A (A->B->A)
    float acc = __ldg(&hb[0]);
#pragma unroll 8
    for (int c = 0; c < HID; c++)
        acc = fmaf(h[n * HID + c], __ldg(&hw[c]), acc);
    int G = *ngp;
    int npg = N / G;
    int g = n / npg, r = n - g * npg;
    for (int d = 0; d < gfd; d++)
        acc = fmaf(__ldg(&gfeat[(g * gfd + d) * npg + r]), __ldg(&hw[HID + d]), acc);
    out[n] = acc;
}

// ---------------- launch ----------------
extern "C" void kernel_launch(void* const* d_in, const int* in_sizes, int n_in,
                              void* d_out, int out_size) {
    const float* x     = (const float*)d_in[0];
    const int*   eidx  = (const int*)d_in[1];
    const float* eattr = (const float*)d_in[2];
    const int*   ngp   = (const int*)d_in[3];
    const float* gfeat = (const float*)d_in[4];
    const float* src_w = (const float*)d_in[5];
    const float* src_b = (const float*)d_in[6];

    int N   = in_sizes[0] / INDIM;
    int E   = in_sizes[1] / 2;
    int gfd = in_sizes[4] / N;

    const int* src = eidx;
    const int* dst = eidx + E;

    // CSR build + permuted edge streams
    k_zero<<<(N + 255) / 256, 256>>>(N);
    k_hist<<<(E + 255) / 256, 256>>>(dst, E);
    int nb = (N + 1023) / 1024;
    k_scan1<<<nb, 1024>>>(N);
    k_scan2<<<1, 32>>>(nb);
    k_scan3<<<nb, 1024>>>(N, E);
    k_scatter<<<(E + 255) / 256, 256>>>(src, dst, (const float4*)eattr, E);

    // h0 = x @ src_w + src_b   (writes g_hA)
    k_inlin<<<(N * HID + 255) / 256, 256>>>(x, src_w, src_b, N);

    // layer 0: hA -> tmp -> hB
    k_agg<<<(N + 7) / 8, 256>>>(0, (const float*)d_in[7], (const float*)d_in[8], N);
    k_mlp<<<(N + 31) / 32, 256>>>(0,
        (const float*)d_in[9],  (const float*)d_in[10],
        (const float*)d_in[11], (const float*)d_in[12],
        (const float*)d_in[13], (const float*)d_in[14], N);

    // layer 1: hB -> tmp -> hA
    k_agg<<<(N + 7) / 8, 256>>>(1, (const float*)d_in[15], (const float*)d_in[16], N);
    k_mlp<<<(N + 31) / 32, 256>>>(1,
        (const float*)d_in[17], (const float*)d_in[18],
        (const float*)d_in[19], (const float*)d_in[20],
        (const float*)d_in[21], (const float*)d_in[22], N);

    // head
    k_head<<<(N + 255) / 256, 256>>>(gfeat, ngp,
        (const float*)d_in[23], (const float*)d_in[24],
        (float*)d_out, N, gfd);
    (void)n_in; (void)out_size;
}

// round 13
// speedup vs baseline: 1.9494x; 1.2739x over previous
#include <cuda_runtime.h>

#define NN    100000
#define EE    1600000
#define HID   64
#define HID2  128
#define EDIM  16
#define INDIM 32

// ---------------- scratch (device globals; no allocation) ----------------
__device__ float  g_hA[NN * HID];
__device__ float  g_hB[NN * HID];
__device__ float  g_tmp[NN * HID];
__device__ int    g_deg[NN];
__device__ int    g_cnt[NN];
__device__ int    g_rowptr[NN + 1];
__device__ int    g_blksum[256];
__device__ int    g_srcp[EE];          // src index permuted to CSR order
__device__ float4 g_eap[EE * 4];       // edge_attr permuted to CSR order (64 B/edge)

// ---------------- cp.async helpers ----------------
__device__ __forceinline__ void cp_async16(void* dst, const void* src) {
    unsigned int d = (unsigned int)__cvta_generic_to_shared(dst);
    asm volatile("cp.async.ca.shared.global [%0], [%1], 16;" :: "r"(d), "l"(src) : "memory");
}
__device__ __forceinline__ void cp_async8(void* dst, const void* src) {
    unsigned int d = (unsigned int)__cvta_generic_to_shared(dst);
    asm volatile("cp.async.ca.shared.global [%0], [%1], 8;" :: "r"(d), "l"(src) : "memory");
}
__device__ __forceinline__ void cp_commit() {
    asm volatile("cp.async.commit_group;" ::: "memory");
}
__device__ __forceinline__ void cp_wait1() {
    asm volatile("cp.async.wait_group 1;" ::: "memory");
}

// ---------------- CSR build ----------------
__global__ void k_zero(int N) {
    int i = blockIdx.x * blockDim.x + threadIdx.x;
    if (i < N) { g_deg[i] = 0; g_cnt[i] = 0; }
}

__global__ void k_hist(const int* __restrict__ dst, int E) {
    int e = blockIdx.x * blockDim.x + threadIdx.x;
    if (e < E) atomicAdd(&g_deg[dst[e]], 1);
}

__global__ void k_scan1(int N) {
    __shared__ int sh[1024];
    int i = blockIdx.x * 1024 + threadIdx.x;
    int v = (i < N) ? g_deg[i] : 0;
    sh[threadIdx.x] = v;
    __syncthreads();
    for (int off = 1; off < 1024; off <<= 1) {
        int add = (threadIdx.x >= off) ? sh[threadIdx.x - off] : 0;
        __syncthreads();
        sh[threadIdx.x] += add;
        __syncthreads();
    }
    if (i < N) g_rowptr[i] = sh[threadIdx.x] - v;     // exclusive
    if (threadIdx.x == 1023) g_blksum[blockIdx.x] = sh[1023];
}

__global__ void k_scan2(int B) {
    if (blockIdx.x == 0 && threadIdx.x == 0) {
        int acc = 0;
        for (int b = 0; b < B; b++) { int t = g_blksum[b]; g_blksum[b] = acc; acc += t; }
    }
}

__global__ void k_scan3(int N, int E) {
    int i = blockIdx.x * 1024 + threadIdx.x;
    if (i < N) g_rowptr[i] += g_blksum[blockIdx.x];
    if (i == 0) g_rowptr[N] = E;
}

// scatter: build CSR-permuted src and edge_attr streams
__global__ void k_scatter(const int* __restrict__ src, const int* __restrict__ dst,
                          const float4* __restrict__ ea, int E) {
    int e = blockIdx.x * blockDim.x + threadIdx.x;
    if (e >= E) return;
    int d = dst[e];
    int p = g_rowptr[d] + atomicAdd(&g_cnt[d], 1);
    g_srcp[p] = src[e];
    float4 a0 = __ldg(ea + e * 4 + 0);
    float4 a1 = __ldg(ea + e * 4 + 1);
    float4 a2 = __ldg(ea + e * 4 + 2);
    float4 a3 = __ldg(ea + e * 4 + 3);
    g_eap[p * 4 + 0] = a0;
    g_eap[p * 4 + 1] = a1;
    g_eap[p * 4 + 2] = a2;
    g_eap[p * 4 + 3] = a3;
}

// ---------------- input linear: h = x @ src_w + src_b ----------------
__global__ void k_inlin(const float* __restrict__ x, const float* __restrict__ w,
                        const float* __restrict__ b, int N) {
    int idx = blockIdx.x * blockDim.x + threadIdx.x;
    if (idx >= N * HID) return;
    int n = idx >> 6, c = idx & 63;
    const float* xr = x + n * INDIM;
    float acc = __ldg(&b[c]);
#pragma unroll
    for (int k = 0; k < INDIM; k++)
        acc = fmaf(__ldg(&xr[k]), __ldg(&w[k * HID + c]), acc);
    g_hA[idx] = acc;
}

// ---------------- aggregation: warp-per-node, cp.async double-buffer --------
// dir=0: read g_hA; dir=1: read g_hB. Writes g_tmp.
// lane owns channels (2*lane, 2*lane+1).
// Per warp, batches of 8 edges staged into smem: attrs 512B (1 cp.async.16/lane),
// h-gathers 8B/lane/edge. 2-stage pipeline, commit/wait_group.
__global__ void __launch_bounds__(256)
k_agg(int dir, const float* __restrict__ ew, const float* __restrict__ ebias, int N) {
    const float* hin = dir ? g_hB : g_hA;
    __shared__ float4 s_attr[8][2][32];       // [warp][stage][8 edges * 4 float4] = 8 KB
    __shared__ float2 s_h[8][2][8][32];       // [warp][stage][edge][lane]        = 32 KB

    int warp = threadIdx.x >> 5, lane = threadIdx.x & 31;
    int n = blockIdx.x * 8 + warp;
    if (n >= N) return;

    // preload ew columns for this lane's two channels
    float2 ewr[EDIM];
#pragma unroll
    for (int k = 0; k < EDIM; k++)
        ewr[k] = __ldg((const float2*)(ew + k * HID) + lane);
    float2 eb = __ldg((const float2*)ebias + lane);
    float2 hs = __ldg((const float2*)(hin + n * HID) + lane);   // self feature

    int beg = g_rowptr[n], end = g_rowptr[n + 1];
    int deg = end - beg;
    float s0 = 0.f, s1 = 0.f, t0 = 0.f, t1 = 0.f;

    // ---- stage helper (inlined twice + in loop via macro) ----
#define STAGE(SIDX, ESTART) do {                                               \
        int _m = end - (ESTART);                                               \
        if (_m > 8) _m = 8;                                                    \
        if (_m > 0) {                                                          \
            if (lane < _m * 4)                                                 \
                cp_async16(&s_attr[warp][SIDX][lane],                          \
                           (const float4*)g_eap + (size_t)(ESTART) * 4 + lane);\
            _Pragma("unroll")                                                  \
            for (int _e = 0; _e < 8; _e++) {                                   \
                if (_e < _m) {                                                 \
                    int _sv = __ldg(&g_srcp[(ESTART) + _e]);                   \
                    cp_async8(&s_h[warp][SIDX][_e][lane],                      \
                              (const float2*)(hin + _sv * HID) + lane);        \
                }                                                              \
            }                                                                  \
        }                                                                      \
        cp_commit();                                                           \
    } while (0)

    int nb = (deg + 7) >> 3;               // number of 8-edge batches
    STAGE(0, beg);
    STAGE(1, beg + 8);

    for (int b = 0; b < nb; b++) {
        cp_wait1();
        __syncwarp();
        int estart = beg + b * 8;
        int m = end - estart; if (m > 8) m = 8;
        int sidx = b & 1;
        for (int e = 0; e < m; e++) {
            const float4* sa = &s_attr[warp][sidx][e * 4];
            float4 a0 = sa[0], a1 = sa[1], a2 = sa[2], a3 = sa[3];
            float2 h = s_h[warp][sidx][e][lane];
            float av[16] = {a0.x, a0.y, a0.z, a0.w, a1.x, a1.y, a1.z, a1.w,
                            a2.x, a2.y, a2.z, a2.w, a3.x, a3.y, a3.z, a3.w};
            float v0 = eb.x, v1 = eb.y;
#pragma unroll
            for (int k = 0; k < EDIM; k++) {
                v0 = fmaf(av[k], ewr[k].x, v0);
                v1 = fmaf(av[k], ewr[k].y, v1);
            }
            // msg = relu(h+v); eps added at the end (softmax shift-invariant).
            // No max-subtraction: msg >= 0 and O(10) -> expf cannot overflow.
            float r0 = fmaxf(h.x + v0, 0.f);
            float r1 = fmaxf(h.y + v1, 0.f);
            float w0 = __expf(r0);
            float w1 = __expf(r1);
            s0 += w0;
            s1 += w1;
            t0 = fmaf(r0, w0, t0);
            t1 = fmaf(r1, w1, t1);
        }
        __syncwarp();                       // all lanes done reading before refill
        STAGE(sidx, beg + (b + 2) * 8);     // commits empty group past the end
    }
#undef STAGE

    float o0 = (s0 > 0.f ? __fdividef(t0, s0) + 1e-7f : 0.f) + hs.x;
    float o1 = (s1 > 0.f ? __fdividef(t1, s1) + 1e-7f : 0.f) + hs.y;
    *((float2*)(g_tmp + n * HID) + lane) = make_float2(o0, o1);
}

// ---------------- MLP: Linear(64->128) -> BN -> ReLU -> Linear(128->64) -> ReLU
// reads g_tmp; dir=0: write g_hB; dir=1: write g_hA.
// 32 nodes per block, 256 threads, register-tiled, float4 LDS
__global__ void __launch_bounds__(256)
k_mlp(int dir,
      const float* __restrict__ w1, const float* __restrict__ b1,
      const float* __restrict__ gam, const float* __restrict__ bet,
      const float* __restrict__ w2, const float* __restrict__ b2, int N) {
    float* outp = dir ? g_hA : g_hB;
    __shared__ float s_in[32][HID];     // 8 KB
    __shared__ float s_hh[32][HID2];    // 16 KB
    int tid = threadIdx.x;
    int base = blockIdx.x * 32;

    // stage 32 node rows (zero-fill past N)
    {
        const float4* src4 = (const float4*)(g_tmp + base * HID);
        float4* dst4 = (float4*)&s_in[0][0];
        long limit4 = (long)(N - base) * (HID / 4);
#pragma unroll
        for (int t = 0; t < 2; t++) {
            int i = tid + t * 256;
            dst4[i] = (i < limit4) ? __ldg(src4 + i) : make_float4(0.f, 0.f, 0.f, 0.f);
        }
    }
    __syncthreads();

    // phase 1: hh = relu(BN(in @ w1 + b1)); thread: 8 nodes x 2 adjacent j
    {
        int jp  = tid & 63;
        int grp = tid >> 6;
        float2 bb = __ldg((const float2*)b1 + jp);
        float a0[8], a1[8];
#pragma unroll
        for (int u = 0; u < 8; u++) { a0[u] = bb.x; a1[u] = bb.y; }
#pragma unroll
        for (int k4 = 0; k4 < HID; k4 += 4) {
            float2 w0 = __ldg((const float2*)(w1 + (k4 + 0) * HID2) + jp);
            float2 w1v = __ldg((const float2*)(w1 + (k4 + 1) * HID2) + jp);
            float2 w2v = __ldg((const float2*)(w1 + (k4 + 2) * HID2) + jp);
            float2 w3 = __ldg((const float2*)(w1 + (k4 + 3) * HID2) + jp);
#pragma unroll
            for (int u = 0; u < 8; u++) {
                float4 xv = *(const float4*)&s_in[grp * 8 + u][k4];
                a0[u] = fmaf(xv.x, w0.x, a0[u]);
                a1[u] = fmaf(xv.x, w0.y, a1[u]);
                a0[u] = fmaf(xv.y, w1v.x, a0[u]);
                a1[u] = fmaf(xv.y, w1v.y, a1[u]);
                a0[u] = fmaf(xv.z, w2v.x, a0[u]);
                a1[u] = fmaf(xv.z, w2v.y, a1[u]);
                a0[u] = fmaf(xv.w, w3.x, a0[u]);
                a1[u] = fmaf(xv.w, w3.y, a1[u]);
            }
        }
        const float BNC = 0.9999950000375f;    // 1/sqrt(1+1e-5)
        float2 gm = __ldg((const float2*)gam + jp);
        float2 bt = __ldg((const float2*)bet + jp);
        float g0 = gm.x * BNC, g1 = gm.y * BNC;
#pragma unroll
        for (int u = 0; u < 8; u++) {
            float2 hv;
            hv.x = fmaxf(fmaf(a0[u], g0, bt.x), 0.f);
            hv.y = fmaxf(fmaf(a1[u], g1, bt.y), 0.f);
            *((float2*)&s_hh[grp * 8 + u][0] + jp) = hv;
        }
    }
    __syncthreads();

    // phase 2: y = relu(hh @ w2 + b2); thread: 4 nodes x 2 adjacent c
    {
        int cp  = tid & 31;
        int grp = tid >> 5;
        float2 bb = __ldg((const float2*)b2 + cp);
        float a0[4], a1[4];
#pragma unroll
        for (int u = 0; u < 4; u++) { a0[u] = bb.x; a1[u] = bb.y; }
#pragma unroll
        for (int k4 = 0; k4 < HID2; k4 += 4) {
            float2 w0 = __ldg((const float2*)(w2 + (k4 + 0) * HID) + cp);
            float2 w1v = __ldg((const float2*)(w2 + (k4 + 1) * HID) + cp);
            float2 w2v = __ldg((const float2*)(w2 + (k4 + 2) * HID) + cp);
            float2 w3 = __ldg((const float2*)(w2 + (k4 + 3) * HID) + cp);
#pragma unroll
            for (int u = 0; u < 4; u++) {
                float4 xv = *(const float4*)&s_hh[grp * 4 + u][k4];
                a0[u] = fmaf(xv.x, w0.x, a0[u]);
                a1[u] = fmaf(xv.x, w0.y, a1[u]);
                a0[u] = fmaf(xv.y, w1v.x, a0[u]);
                a1[u] = fmaf(xv.y, w1v.y, a1[u]);
                a0[u] = fmaf(xv.z, w2v.x, a0[u]);
                a1[u] = fmaf(xv.z, w2v.y, a1[u]);
                a0[u] = fmaf(xv.w, w3.x, a0[u]);
                a1[u] = fmaf(xv.w, w3.y, a1[u]);
            }
        }
#pragma unroll
        for (int u = 0; u < 4; u++) {
            int node = base + grp * 4 + u;
            if (node < N) {
                float2 ov;
                ov.x = fmaxf(a0[u], 0.f);   // outer relu
                ov.y = fmaxf(a1[u], 0.f);
                *((float2*)(outp + node * HID) + cp) = ov;
            }
        }
    }
}

// ---------------- head ----------------
__global__ void k_head(const float* __restrict__ gfeat, const int* __restrict__ ngp,
                       const float* __restrict__ hw, const float* __restrict__ hb,
                       float* __restrict__ out, int N, int gfd) {
    int n = blockIdx.x * blockDim.x + threadIdx.x;
    if (n >= N) return;
    const float* h = g_hA;   // final features land in A (A->B->A)
    float acc = __ldg(&hb[0]);
#pragma unroll 8
    for (int c = 0; c < HID; c++)
        acc = fmaf(h[n * HID + c], __ldg(&hw[c]), acc);
    int G = *ngp;
    int npg = N / G;
    int g = n / npg, r = n - g * npg;
    for (int d = 0; d < gfd; d++)
        acc = fmaf(__ldg(&gfeat[(g * gfd + d) * npg + r]), __ldg(&hw[HID + d]), acc);
    out[n] = acc;
}

// ---------------- launch ----------------
extern "C" void kernel_launch(void* const* d_in, const int* in_sizes, int n_in,
                              void* d_out, int out_size) {
    const float* x     = (const float*)d_in[0];
    const int*   eidx  = (const int*)d_in[1];
    const float* eattr = (const float*)d_in[2];
    const int*   ngp   = (const int*)d_in[3];
    const float* gfeat = (const float*)d_in[4];
    const float* src_w = (const float*)d_in[5];
    const float* src_b = (const float*)d_in[6];

    int N   = in_sizes[0] / INDIM;
    int E   = in_sizes[1] / 2;
    int gfd = in_sizes[4] / N;

    const int* src = eidx;
    const int* dst = eidx + E;

    // CSR build + permuted edge streams
    k_zero<<<(N + 255) / 256, 256>>>(N);
    k_hist<<<(E + 255) / 256, 256>>>(dst, E);
    int nb = (N + 1023) / 1024;
    k_scan1<<<nb, 1024>>>(N);
    k_scan2<<<1, 32>>>(nb);
    k_scan3<<<nb, 1024>>>(N, E);
    k_scatter<<<(E + 255) / 256, 256>>>(src, dst, (const float4*)eattr, E);

    // h0 = x @ src_w + src_b   (writes g_hA)
    k_inlin<<<(N * HID + 255) / 256, 256>>>(x, src_w, src_b, N);

    // layer 0: hA -> tmp -> hB
    k_agg<<<(N + 7) / 8, 256>>>(0, (const float*)d_in[7], (const float*)d_in[8], N);
    k_mlp<<<(N + 31) / 32, 256>>>(0,
        (const float*)d_in[9],  (const float*)d_in[10],
        (const float*)d_in[11], (const float*)d_in[12],
        (const float*)d_in[13], (const float*)d_in[14], N);

    // layer 1: hB -> tmp -> hA
    k_agg<<<(N + 7) / 8, 256>>>(1, (const float*)d_in[15], (const float*)d_in[16], N);
    k_mlp<<<(N + 31) / 32, 256>>>(1,
        (const float*)d_in[17], (const float*)d_in[18],
        (const float*)d_in[19], (const float*)d_in[20],
        (const float*)d_in[21], (const float*)d_in[22], N);

    // head
    k_head<<<(N + 255) / 256, 256>>>(gfeat, ngp,
        (const float*)d_in[23], (const float*)d_in[24],
        (float*)d_out, N, gfd);
    (void)n_in; (void)out_size;
}